// round 8
// baseline (speedup 1.0000x reference)
#include <cuda_runtime.h>
#include <cuda_bf16.h>
#include <cstddef>

// Problem constants: B=512, T=1024, H=128, LAT=16, COND=1, OUT=12
#define BATCH 512
#define TT    1024
#define HID   128
#define GATES 512       // 4*H
#define OUTD  12

typedef unsigned long long ull;

// Device scratch (static __device__ arrays are the sanctioned alloc-free workaround)
__device__ float g_xproj[BATCH * GATES];                      // [b][j]
__device__ float g_hs[(size_t)BATCH * TT * HID];              // [b][t][k]  (268 MB)

// ---------------- helpers ----------------
__device__ __forceinline__ ull ffma2(ull a, ull b, ull c) {
    ull d;
    asm("fma.rn.f32x2 %0, %1, %2, %3;" : "=l"(d) : "l"(a), "l"(b), "l"(c));
    return d;
}
__device__ __forceinline__ ull pack2(float lo, float hi) {
    ull d;
    asm("mov.b64 %0, {%1, %2};" : "=l"(d) : "f"(lo), "f"(hi));
    return d;
}
__device__ __forceinline__ float pairsum(ull a) {
    float lo, hi;
    asm("mov.b64 {%0, %1}, %2;" : "=f"(lo), "=f"(hi) : "l"(a));
    return lo + hi;
}
__device__ __forceinline__ float sigmoidf_(float x) {
    float e = __expf(-x);
    return __fdividef(1.f, 1.f + e);
}
__device__ __forceinline__ float tanhf_(float x) {
    float e = __expf(2.f * x);
    return 1.f - __fdividef(2.f, 1.f + e);
}

// dummy no-op kernel: shifts ncu's capture window onto k2_lstm
__global__ void k_nop() {}

// ---------------- k1: x = latent@Ws^T + bs ; xproj = x@Wih^T + bih + bhh ----------------
// 128 blocks x 512 threads; each block handles BPB=4 batch rows.
#define BPB 4
__global__ __launch_bounds__(512)
void k1_xproj(const float* __restrict__ z, const float* __restrict__ c,
              const float* __restrict__ Ws, const float* __restrict__ bs,
              const float* __restrict__ Wih, const float* __restrict__ bih,
              const float* __restrict__ bhh) {
    __shared__ float sWs[HID * 17];
    __shared__ float slat[BPB * 17];
    __shared__ float sx[BPB][HID];
    const int tid = threadIdx.x;
    const int b0 = blockIdx.x * BPB;

    for (int i = tid; i < HID * 17; i += 512) sWs[i] = Ws[i];
    if (tid < BPB * 17) {
        int b = tid / 17, q = tid - b * 17;
        slat[tid] = (q < 16) ? z[(b0 + b) * 16 + q] : c[b0 + b];
    }
    __syncthreads();

    // x[b][hcol]: 4*128 = 512 entries, 1 per thread
    {
        int b = tid >> 7, hcol = tid & 127;
        float acc = bs[hcol];
        #pragma unroll
        for (int l = 0; l < 17; l++) acc += sWs[hcol * 17 + l] * slat[b * 17 + l];
        sx[b][hcol] = acc;
    }
    __syncthreads();

    // xproj: thread j = gate row
    const int j = tid;
    float acc[BPB];
    float base = bih[j] + bhh[j];
    #pragma unroll
    for (int b = 0; b < BPB; b++) acc[b] = base;
    const float4* wr = (const float4*)(Wih + j * HID);
    #pragma unroll 8
    for (int u = 0; u < 32; u++) {
        float4 w = wr[u];
        #pragma unroll
        for (int b = 0; b < BPB; b++) {
            acc[b] += w.x * sx[b][4*u] + w.y * sx[b][4*u+1]
                    + w.z * sx[b][4*u+2] + w.w * sx[b][4*u+3];
        }
    }
    #pragma unroll
    for (int b = 0; b < BPB; b++) g_xproj[(b0 + b) * GATES + j] = acc[b];
}

// ---------------- k2: the 1024-step recurrence ----------------
// 128 CTAs x 512 threads (16 warps, 4/SMSP). CTA owns 4 batch rows.
// Thread j owns ONE gate row j of Whh: chunks u<12 in registers (48 regs),
// u=12..31 in smem (160 KB). 4 warps/SMSP hide the activation/exchange tail
// under other warps' FFMA2 issue; per-thread work halves vs the 256-thread
// version, register pressure drops to ~90 (no spill risk).
// smem: wsm [20][512] ulonglong2 (163840 B) | hbuf [2][4][128] f32 (4096 B)
//       | gbuf [4][512] f32 (8192 B)  => 176128 B
#define K2_SMEM 176128
#define UREG 12

__global__ __launch_bounds__(512, 1)
void k2_lstm(const float* __restrict__ Whh) {
    extern __shared__ __align__(16) unsigned char sraw[];
    ulonglong2* wsm = (ulonglong2*)sraw;                      // [(u-UREG)*512 + j]
    float* hbuf = (float*)(sraw + 163840);                    // [par][r][k]
    float* gbuf = (float*)(sraw + 163840 + 4096);             // [r][j]

    const int j = threadIdx.x;                                // gate row 0..511
    const int b0 = blockIdx.x * 4;

    // weight row j: u<UREG -> registers, rest -> smem
    ull war[2 * UREG];
    {
        const ulonglong2* row = (const ulonglong2*)(Whh + j * HID);
        #pragma unroll
        for (int u = 0; u < UREG; u++) {
            ulonglong2 t = row[u];
            war[2*u] = t.x; war[2*u+1] = t.y;
        }
        #pragma unroll
        for (int u = UREG; u < 32; u++) wsm[(u - UREG) * 512 + j] = row[u];
    }

    // Constant input projection for this gate row, 4 batch rows
    float xp[4];
    #pragma unroll
    for (int r = 0; r < 4; r++) xp[r] = g_xproj[(b0 + r) * GATES + j];

    // zero both h buffers (2*512 floats)
    hbuf[j] = 0.f;
    hbuf[j + 512] = 0.f;
    __syncthreads();

    // activation type for this gate row: 0..127 i(sig), 128..255 f(sig),
    // 256..383 g(tanh), 384..511 o(sig)
    const bool isg = (j >= 256) && (j < 384);

    // phase-B ownership: cell (rr, kk)
    const int kk = j & 127;
    const int rr = j >> 7;
    float cc = 0.f;
    float* hsp = g_hs + (size_t)(b0 + rr) * TT * HID + kk;

    int par = 0;
    for (int t = 0; t < TT; t++) {
        // ---- phase A: gate j for 4 rows = xp + Whh[j,:] . h[r,:] ----
        ull acc[4];
        #pragma unroll
        for (int r = 0; r < 4; r++) acc[r] = pack2(xp[r], 0.f);
        const ulonglong2* hb = (const ulonglong2*)(hbuf + par * 512);
        #pragma unroll
        for (int u = 0; u < UREG; u++) {
            #pragma unroll
            for (int r = 0; r < 4; r++) {
                ulonglong2 h2 = hb[r * 32 + u];          // broadcast LDS.128
                acc[r] = ffma2(war[2*u],   h2.x, acc[r]);
                acc[r] = ffma2(war[2*u+1], h2.y, acc[r]);
            }
        }
        #pragma unroll
        for (int u = UREG; u < 32; u++) {
            ulonglong2 wb = wsm[(u - UREG) * 512 + j];
            #pragma unroll
            for (int r = 0; r < 4; r++) {
                ulonglong2 h2 = hb[r * 32 + u];          // broadcast LDS.128
                acc[r] = ffma2(wb.x, h2.x, acc[r]);
                acc[r] = ffma2(wb.y, h2.y, acc[r]);
            }
        }
        #pragma unroll
        for (int r = 0; r < 4; r++) {
            float v = pairsum(acc[r]);
            gbuf[r * 512 + j] = isg ? tanhf_(v) : sigmoidf_(v);
        }
        __syncthreads();

        // ---- phase B: cell update for (rr, kk) ----
        float hv;
        {
            const float* gb = gbuf + rr * 512;
            float iv = gb[kk], fv = gb[128 + kk], gv = gb[256 + kk], ov = gb[384 + kk];
            cc = fv * cc + iv * gv;
            hv = ov * tanhf_(cc);
            hbuf[(par ^ 1) * 512 + rr * 128 + kk] = hv;
        }
        __syncthreads();
        // deferred global store: overlaps next step's FMA
        hsp[t * HID] = hv;
        par ^= 1;
    }
}

// ---------------- k3: out[b,t,:] = hs[b,t,:] @ Wout^T + bout ----------------
__global__ __launch_bounds__(256)
void k3_out(const float* __restrict__ Wout, const float* __restrict__ bout,
            float* __restrict__ out) {
    __shared__ float4 wsm[OUTD][32];
    __shared__ float bo[OUTD];
    int tid = threadIdx.x;
    for (int i = tid; i < OUTD * 32; i += 256) wsm[i / 32][i % 32] = ((const float4*)Wout)[i];
    if (tid < OUTD) bo[tid] = bout[tid];
    __syncthreads();

    unsigned bt = blockIdx.x * 256 + tid;                // < 524288 exactly
    const float4* hr = (const float4*)(g_hs + (size_t)bt * HID);
    float acc[OUTD];
    #pragma unroll
    for (int o = 0; o < OUTD; o++) acc[o] = bo[o];
    #pragma unroll 4
    for (int u = 0; u < 32; u++) {
        float4 h = hr[u];
        #pragma unroll
        for (int o = 0; o < OUTD; o++) {
            float4 wv = wsm[o][u];
            acc[o] += h.x * wv.x + h.y * wv.y + h.z * wv.z + h.w * wv.w;
        }
    }
    float* op = out + (size_t)bt * OUTD;
    #pragma unroll
    for (int o = 0; o < OUTD; o++) op[o] = acc[o];
}

// ---------------- launcher ----------------
extern "C" void kernel_launch(void* const* d_in, const int* in_sizes, int n_in,
                              void* d_out, int out_size) {
    (void)in_sizes; (void)n_in; (void)out_size;
    const float* z   = (const float*)d_in[0];
    const float* c   = (const float*)d_in[1];
    const float* Ws  = (const float*)d_in[2];
    const float* bs  = (const float*)d_in[3];
    const float* Wih = (const float*)d_in[4];
    const float* bih = (const float*)d_in[5];
    const float* Whh = (const float*)d_in[6];
    const float* bhh = (const float*)d_in[7];
    const float* Wo  = (const float*)d_in[8];
    const float* bo  = (const float*)d_in[9];
    float* out = (float*)d_out;

    cudaFuncSetAttribute(k2_lstm, cudaFuncAttributeMaxDynamicSharedMemorySize, K2_SMEM);

    k1_xproj<<<BATCH / BPB, 512>>>(z, c, Ws, bs, Wih, bih, bhh);
    // 3 no-op launches: one harness launch precedes ours, so capture idx 5 = k2
    k_nop<<<1, 32>>>();
    k_nop<<<1, 32>>>();
    k_nop<<<1, 32>>>();
    k2_lstm<<<128, 512, K2_SMEM>>>(Whh);
    k3_out<<<(BATCH * TT) / 256, 256>>>(Wo, bo, out);
}

// round 9
// speedup vs baseline: 1.5031x; 1.5031x over previous
#include <cuda_runtime.h>
#include <cuda_bf16.h>
#include <cstddef>

// Problem constants: B=512, T=1024, H=128, LAT=16, COND=1, OUT=12
#define BATCH 512
#define TT    1024
#define HID   128
#define GATES 512       // 4*H
#define OUTD  12

typedef unsigned long long ull;

// Device scratch (static __device__ arrays are the sanctioned alloc-free workaround)
__device__ float g_hs[(size_t)BATCH * TT * HID];              // [b][t][k]  (268 MB)

// ---------------- helpers ----------------
__device__ __forceinline__ ull ffma2(ull a, ull b, ull c) {
    ull d;
    asm("fma.rn.f32x2 %0, %1, %2, %3;" : "=l"(d) : "l"(a), "l"(b), "l"(c));
    return d;
}
__device__ __forceinline__ ull pack2(float lo, float hi) {
    ull d;
    asm("mov.b64 %0, {%1, %2};" : "=l"(d) : "f"(lo), "f"(hi));
    return d;
}
__device__ __forceinline__ float pairsum(ull a) {
    float lo, hi;
    asm("mov.b64 {%0, %1}, %2;" : "=f"(lo), "=f"(hi) : "l"(a));
    return lo + hi;
}
__device__ __forceinline__ float sigmoidf_(float x) {
    float e = __expf(-x);
    return __fdividef(1.f, 1.f + e);
}
__device__ __forceinline__ float tanhf_(float x) {
    float e = __expf(2.f * x);
    return 1.f - __fdividef(2.f, 1.f + e);
}

// dummy no-op kernel: ncu captures absolute launch #6; harness issues 2 before
// ours, so 3 nops put k2 (our 4th launch) at #6.
__global__ void k_nop() {}

// ---------------- k2: xproj prologue + the 1024-step recurrence ----------------
// 128 CTAs x 256 threads. CTA owns 4 batch rows. Thread j owns gates j and j+256.
// Gate-A (j): all 128 Whh weights in registers.
// Gate-B (j+256): first 32 weights (u<8) in registers, rest (u=8..31) in smem.
// gbuf holds float2(gateA, gateB) per (row, thread): STS.64/LDS.64 exchange.
// smem: wsmB [24][256] ulonglong2 (98304 B) | hbuf [2][4][128] f32 (4096 B)
//       | gbuf [4][256] float2 (8192 B)  => 110592 B
#define K2_SMEM 110592

__global__ __launch_bounds__(256, 1)
void k2_lstm(const float* __restrict__ z, const float* __restrict__ c,
             const float* __restrict__ Ws, const float* __restrict__ bs,
             const float* __restrict__ Wih, const float* __restrict__ bih,
             const float* __restrict__ bhh, const float* __restrict__ Whh) {
    extern __shared__ __align__(16) unsigned char sraw[];
    ulonglong2* wsmB = (ulonglong2*)sraw;                     // [u-8][tid]
    float* hbuf = (float*)(sraw + 98304);                     // [par][r][k]
    float2* g2  = (float2*)(sraw + 98304 + 4096);             // [r][j] {gateA,gateB}
    float* scr  = (float*)(sraw + 98304 + 4096);              // prologue scratch (aliases g2)

    const int tid = threadIdx.x;
    const int b0 = blockIdx.x * 4;

    // ===== prologue: xproj for this CTA's 4 batch rows (replaces old k1) =====
    // scr layout: slat [4*17] | sx [4*128] starting at +128
    float* slat = scr;
    float* sx   = scr + 128;
    if (tid < 68) {
        int r = tid / 17, q = tid - r * 17;
        slat[tid] = (q < 16) ? z[(b0 + r) * 16 + q] : c[b0 + r];
    }
    __syncthreads();
    #pragma unroll
    for (int i = 0; i < 2; i++) {
        int idx = tid + i * 256;
        int r = idx >> 7, hcol = idx & 127;
        float acc = bs[hcol];
        #pragma unroll
        for (int l = 0; l < 17; l++) acc += Ws[hcol * 17 + l] * slat[r * 17 + l];
        sx[r * 128 + hcol] = acc;
    }
    __syncthreads();
    float xpA[4], xpB[4];
    {
        float bA = bih[tid] + bhh[tid];
        float bB = bih[tid + 256] + bhh[tid + 256];
        #pragma unroll
        for (int r = 0; r < 4; r++) { xpA[r] = bA; xpB[r] = bB; }
        const float4* wA = (const float4*)(Wih + tid * HID);
        const float4* wB = (const float4*)(Wih + (tid + 256) * HID);
        #pragma unroll 4
        for (int u = 0; u < 32; u++) {
            float4 a = wA[u];
            float4 b = wB[u];
            #pragma unroll
            for (int r = 0; r < 4; r++) {
                float4 hx = ((const float4*)(sx + r * 128))[u];
                xpA[r] += a.x * hx.x + a.y * hx.y + a.z * hx.z + a.w * hx.w;
                xpB[r] += b.x * hx.x + b.y * hx.y + b.z * hx.z + b.w * hx.w;
            }
        }
    }
    __syncthreads();   // scr dead; g2 region free for steady loop

    // ===== weight staging =====
    // Gate-A weights -> registers (64 f32x2 pairs = 128 regs)
    ull wa[64];
    {
        const ulonglong2* rowA = (const ulonglong2*)(Whh + tid * HID);
        #pragma unroll
        for (int u = 0; u < 32; u++) {
            ulonglong2 t = rowA[u];
            wa[2*u] = t.x; wa[2*u+1] = t.y;
        }
    }
    // Gate-B weights: u<8 -> registers (16 pairs = 32 regs), u>=8 -> smem
    ull wbr[16];
    {
        const ulonglong2* rowB = (const ulonglong2*)(Whh + (tid + 256) * HID);
        #pragma unroll
        for (int u = 0; u < 8; u++) {
            ulonglong2 t = rowB[u];
            wbr[2*u] = t.x; wbr[2*u+1] = t.y;
        }
        #pragma unroll
        for (int u = 8; u < 32; u++) wsmB[(u - 8) * 256 + tid] = rowB[u];
    }

    // zero both h buffers
    #pragma unroll
    for (int i = 0; i < 4; i++) hbuf[tid + 256 * i] = 0.f;
    __syncthreads();

    // phase-B ownership: cells (rlo, kk) and (rlo+2, kk)
    const int kk = tid & 127;
    const int rlo = tid >> 7;   // 0 or 1
    float cA = 0.f, cB = 0.f;
    float* hsA = g_hs + (size_t)(b0 + rlo) * TT * HID + kk;
    float* hsB = g_hs + (size_t)(b0 + rlo + 2) * TT * HID + kk;
    const bool isg = (tid < 128);   // gate-B is 'g' (tanh) for j<128, else 'o' (sigmoid)

    int par = 0;
    for (int t = 0; t < TT; t++) {
        // ---- phase A: gates = xproj + h @ Whh^T ----
        ull a0[4], a1[4];
        #pragma unroll
        for (int r = 0; r < 4; r++) { a0[r] = pack2(xpA[r], 0.f); a1[r] = pack2(xpB[r], 0.f); }
        const ulonglong2* hb = (const ulonglong2*)(hbuf + par * 512);
        #pragma unroll
        for (int u = 0; u < 8; u++) {
            #pragma unroll
            for (int r = 0; r < 4; r++) {
                ulonglong2 h2 = hb[r * 32 + u];          // broadcast LDS.128
                a0[r] = ffma2(wa[2*u],    h2.x, a0[r]);
                a0[r] = ffma2(wa[2*u+1],  h2.y, a0[r]);
                a1[r] = ffma2(wbr[2*u],   h2.x, a1[r]);
                a1[r] = ffma2(wbr[2*u+1], h2.y, a1[r]);
            }
        }
        #pragma unroll
        for (int u = 8; u < 32; u++) {
            ulonglong2 wb = wsmB[(u - 8) * 256 + tid];
            #pragma unroll
            for (int r = 0; r < 4; r++) {
                ulonglong2 h2 = hb[r * 32 + u];          // broadcast LDS.128
                a0[r] = ffma2(wa[2*u],   h2.x, a0[r]);
                a0[r] = ffma2(wa[2*u+1], h2.y, a0[r]);
                a1[r] = ffma2(wb.x,      h2.x, a1[r]);
                a1[r] = ffma2(wb.y,      h2.y, a1[r]);
            }
        }
        #pragma unroll
        for (int r = 0; r < 4; r++) {
            float gA = pairsum(a0[r]);                   // gate i or f -> sigmoid
            float gB = pairsum(a1[r]);                   // gate g -> tanh, o -> sigmoid
            float aA = sigmoidf_(gA);
            float aB = isg ? tanhf_(gB) : sigmoidf_(gB);
            g2[r * 256 + tid] = make_float2(aA, aB);     // STS.64
        }
        __syncthreads();

        // ---- phase B: cell update for 2 cells (i=A[k], g=B[k], f=A[k+128], o=B[k+128]) ----
        float hA, hB;
        {
            float2 p0 = g2[rlo * 256 + kk];
            float2 q0 = g2[rlo * 256 + 128 + kk];
            float2 p1 = g2[(rlo + 2) * 256 + kk];
            float2 q1 = g2[(rlo + 2) * 256 + 128 + kk];

            cA = q0.x * cA + p0.x * p0.y;
            cB = q1.x * cB + p1.x * p1.y;
            hA = q0.y * tanhf_(cA);
            hB = q1.y * tanhf_(cB);

            float* hn = hbuf + (par ^ 1) * 512;
            hn[rlo * 128 + kk]       = hA;
            hn[(rlo + 2) * 128 + kk] = hB;
        }
        __syncthreads();
        // deferred global stores: overlap with next step's FMA
        hsA[t * HID] = hA;
        hsB[t * HID] = hB;
        par ^= 1;
    }
}

// ---------------- k3: out[b,t,:] = hs[b,t,:] @ Wout^T + bout ----------------
__global__ __launch_bounds__(256)
void k3_out(const float* __restrict__ Wout, const float* __restrict__ bout,
            float* __restrict__ out) {
    __shared__ float4 wsm[OUTD][32];
    __shared__ float bo[OUTD];
    int tid = threadIdx.x;
    for (int i = tid; i < OUTD * 32; i += 256) wsm[i / 32][i % 32] = ((const float4*)Wout)[i];
    if (tid < OUTD) bo[tid] = bout[tid];
    __syncthreads();

    unsigned bt = blockIdx.x * 256 + tid;                // < 524288 exactly
    const float4* hr = (const float4*)(g_hs + (size_t)bt * HID);
    float acc[OUTD];
    #pragma unroll
    for (int o = 0; o < OUTD; o++) acc[o] = bo[o];
    #pragma unroll 4
    for (int u = 0; u < 32; u++) {
        float4 h = hr[u];
        #pragma unroll
        for (int o = 0; o < OUTD; o++) {
            float4 wv = wsm[o][u];
            acc[o] += h.x * wv.x + h.y * wv.y + h.z * wv.z + h.w * wv.w;
        }
    }
    float* op = out + (size_t)bt * OUTD;
    #pragma unroll
    for (int o = 0; o < OUTD; o++) op[o] = acc[o];
}

// ---------------- launcher ----------------
extern "C" void kernel_launch(void* const* d_in, const int* in_sizes, int n_in,
                              void* d_out, int out_size) {
    (void)in_sizes; (void)n_in; (void)out_size;
    const float* z   = (const float*)d_in[0];
    const float* c   = (const float*)d_in[1];
    const float* Ws  = (const float*)d_in[2];
    const float* bs  = (const float*)d_in[3];
    const float* Wih = (const float*)d_in[4];
    const float* bih = (const float*)d_in[5];
    const float* Whh = (const float*)d_in[6];
    const float* bhh = (const float*)d_in[7];
    const float* Wo  = (const float*)d_in[8];
    const float* bo  = (const float*)d_in[9];
    float* out = (float*)d_out;

    cudaFuncSetAttribute(k2_lstm, cudaFuncAttributeMaxDynamicSharedMemorySize, K2_SMEM);

    // 3 no-op launches: harness issues 2 launches before ours, ncu captures
    // absolute launch #6 -> k2 must be our 4th launch.
    k_nop<<<1, 32>>>();
    k_nop<<<1, 32>>>();
    k_nop<<<1, 32>>>();
    k2_lstm<<<128, 256, K2_SMEM>>>(z, c, Ws, bs, Wih, bih, bhh, Whh);
    k3_out<<<(BATCH * TT) / 256, 256>>>(Wo, bo, out);
}